// round 4
// baseline (speedup 1.0000x reference)
#include <cuda_runtime.h>

#define WIN 11
#define PAD 5
#define TX 32
#define TY 64
#define INX 42        // TX + 2*PAD
#define INY 74        // TY + 2*PAD
#define IMG_H 512
#define IMG_W 512
#define NT 256

// loss constants
#define C1V 1.0e-4f
#define C2V 9.0e-4f
#define EPS2 1.0e-12f
#define A_CHARB 0.3f
#define A_SSIM  0.6f
// alpha_mse * 20 = 2.0 folded in combine

// Normalized 11-tap Gaussian (sigma=1.5), derived in double precision.
// Matches the reference's expf/normalize to ~1e-7 (tolerance is 1e-3).
__device__ __constant__ const float c_dummy = 0.f; // keep nvcc happy about empty constant use
#define W0 0.00102838f
#define W1 0.00759876f
#define W2 0.03600078f
#define W3 0.10936070f
#define W4 0.21300554f
#define W5 0.26601173f

__device__ __forceinline__ float gw(int k) {
    // k is a compile-time constant under full unroll -> folds to an immediate
    switch (k) {
        case 0:  return W0;
        case 1:  return W1;
        case 2:  return W2;
        case 3:  return W3;
        case 4:  return W4;
        case 5:  return W5;
        case 6:  return W4;
        case 7:  return W3;
        case 8:  return W2;
        case 9:  return W1;
        default: return W0;
    }
}

struct SmemLayout {
    float2 in[INY][43];    // (x, y) interleaved, stride 43 (86 banks, gcd(86,32)=2 -> conflict-free row walk)
    float4 h4[INY][33];    // (hx, hy, hxx, hyy), stride 33
    float  h1[INY][33];    // hxy
};
#define SMEM_BYTES ((int)sizeof(SmemLayout))

__global__ __launch_bounds__(NT, 3)
void ssim_loss_kernel(const float* __restrict__ pred,
                      const float* __restrict__ targ,
                      float* __restrict__ out) {
    extern __shared__ char smem_raw[];
    SmemLayout* S = reinterpret_cast<SmemLayout*>(smem_raw);

    const int tid = threadIdx.x;
    const int tile_x = blockIdx.x * TX;
    const int tile_y = blockIdx.y * TY;
    const int plane = blockIdx.z;

    const float* __restrict__ px = pred + (size_t)plane * IMG_H * IMG_W;
    const float* __restrict__ py = targ + (size_t)plane * IMG_H * IMG_W;
    float* __restrict__ po = out + (size_t)plane * IMG_H * IMG_W;

    // ---- load halo tile, zero-padded (matches conv zero padding) ----
    #pragma unroll 1
    for (int idx = tid; idx < INY * INX; idx += NT) {
        int r = idx / INX, cc = idx - r * INX;
        int gr = tile_y + r - PAD;
        int gc = tile_x + cc - PAD;
        float2 v = make_float2(0.f, 0.f);
        if (gr >= 0 && gr < IMG_H && gc >= 0 && gc < IMG_W) {
            size_t off = (size_t)gr * IMG_W + gc;
            v.x = px[off];
            v.y = py[off];
        }
        S->in[r][cc] = v;
    }
    __syncthreads();

    // ---- horizontal blur: sliding window, 8 outputs per unit ----
    // unit u: r = u % INY, chunk = u / INY (4 chunks of 8 columns). 296 units.
    #pragma unroll 1
    for (int u = tid; u < INY * 4; u += NT) {
        const int r = u % INY;
        const int c0 = (u / INY) * 8;

        float ax[8], ay[8], axx[8], ayy[8], axy[8];
        #pragma unroll
        for (int j = 0; j < 8; j++) { ax[j]=0.f; ay[j]=0.f; axx[j]=0.f; ayy[j]=0.f; axy[j]=0.f; }

        #pragma unroll
        for (int i = 0; i < 18; i++) {
            float2 v = S->in[r][c0 + i];
            float xx = v.x * v.x;
            float yy = v.y * v.y;
            float xy = v.x * v.y;
            #pragma unroll
            for (int j = 0; j < 8; j++) {
                const int k = i - j;
                if (k >= 0 && k < WIN) {
                    const float wk = gw(k);
                    ax[j]  = fmaf(wk, v.x, ax[j]);
                    ay[j]  = fmaf(wk, v.y, ay[j]);
                    axx[j] = fmaf(wk, xx,  axx[j]);
                    ayy[j] = fmaf(wk, yy,  ayy[j]);
                    axy[j] = fmaf(wk, xy,  axy[j]);
                }
            }
        }
        #pragma unroll
        for (int j = 0; j < 8; j++) {
            S->h4[r][c0 + j] = make_float4(ax[j], ay[j], axx[j], ayy[j]);
            S->h1[r][c0 + j] = axy[j];
        }
    }
    __syncthreads();

    // ---- vertical blur: each thread owns 8 output rows of one column ----
    const int c  = tid & (TX - 1);
    const int r0 = (tid >> 5) * 8;     // 0,8,...,56

    float ax[8], ay[8], axx[8], ayy[8], axy[8];
    #pragma unroll
    for (int j = 0; j < 8; j++) { ax[j]=0.f; ay[j]=0.f; axx[j]=0.f; ayy[j]=0.f; axy[j]=0.f; }

    #pragma unroll
    for (int i = 0; i < 18; i++) {
        float4 h = S->h4[r0 + i][c];
        float hxy = S->h1[r0 + i][c];
        #pragma unroll
        for (int j = 0; j < 8; j++) {
            const int k = i - j;
            if (k >= 0 && k < WIN) {
                const float wk = gw(k);
                ax[j]  = fmaf(wk, h.x, ax[j]);
                ay[j]  = fmaf(wk, h.y, ay[j]);
                axx[j] = fmaf(wk, h.z, axx[j]);
                ayy[j] = fmaf(wk, h.w, ayy[j]);
                axy[j] = fmaf(wk, hxy, axy[j]);
            }
        }
    }

    // ---- elementwise combine + store ----
    #pragma unroll
    for (int j = 0; j < 8; j++) {
        float mu_x = ax[j];
        float mu_y = ay[j];

        float mxy = mu_x * mu_y;
        float s2x = axx[j] - mu_x * mu_x;
        float s2y = ayy[j] - mu_y * mu_y;
        float sxy = axy[j] - mxy;

        float A1 = 2.f * mxy + C1V;
        float A2 = 2.f * sxy + C2V;
        float B1 = mu_x * mu_x + mu_y * mu_y + C1V;
        float B2 = s2x + s2y + C2V;
        float ssim = __fdividef(A1, B1) * __fdividef(A2, B2);

        float2 v = S->in[r0 + j + PAD][c + PAD];
        float d = v.x - v.y;
        float charb = sqrtf(fmaf(d, d, EPS2));

        float res = A_CHARB * charb + 2.0f * (d * d) + A_SSIM * (1.f - ssim);

        po[(size_t)(tile_y + r0 + j) * IMG_W + (tile_x + c)] = res;
    }
}

extern "C" void kernel_launch(void* const* d_in, const int* in_sizes, int n_in,
                              void* d_out, int out_size) {
    const float* pred = (const float*)d_in[0];
    const float* targ = (const float*)d_in[1];
    float* out = (float*)d_out;

    int planes = in_sizes[0] / (IMG_H * IMG_W);   // 48

    static bool attr_set = false;
    if (!attr_set) {
        cudaFuncSetAttribute(ssim_loss_kernel,
                             cudaFuncAttributeMaxDynamicSharedMemorySize, SMEM_BYTES);
        attr_set = true;
    }

    dim3 grid(IMG_W / TX, IMG_H / TY, planes);
    ssim_loss_kernel<<<grid, NT, SMEM_BYTES>>>(pred, targ, out);
}

// round 6
// speedup vs baseline: 1.1310x; 1.1310x over previous
#include <cuda_runtime.h>

#define WIN 11
#define PAD 5
#define TX 32
#define TY 32
#define INX 42        // TX + 2*PAD
#define INY 42        // TY + 2*PAD
#define IMG_H 512
#define IMG_W 512
#define NT 256

// loss constants
#define C1V 1.0e-4f
#define C2V 9.0e-4f
#define EPS2 1.0e-12f
#define A_CHARB 0.3f
#define A_SSIM  0.6f
// alpha_mse * 20 = 2.0 folded in combine

// Normalized 11-tap Gaussian (sigma=1.5), double-precision derived.
#define W0 0.00102838f
#define W1 0.00759876f
#define W2 0.03600078f
#define W3 0.10936070f
#define W4 0.21300554f
#define W5 0.26601173f

typedef unsigned long long u64;

__device__ __forceinline__ float gw(int k) {
    switch (k) {
        case 0:  return W0;
        case 1:  return W1;
        case 2:  return W2;
        case 3:  return W3;
        case 4:  return W4;
        case 5:  return W5;
        case 6:  return W4;
        case 7:  return W3;
        case 8:  return W2;
        case 9:  return W1;
        default: return W0;
    }
}

// packed (w, w) for f32x2 FMA; folds to a compile-time 64-bit constant
__device__ __forceinline__ u64 gwp(int k) {
    unsigned u = __float_as_uint(gw(k));
    return ((u64)u << 32) | (u64)u;
}

__device__ __forceinline__ void fma2(u64& acc, u64 a, u64 b) {
    asm("fma.rn.f32x2 %0, %1, %2, %0;" : "+l"(acc) : "l"(a), "l"(b));
}

__device__ __forceinline__ u64 pack2(float lo, float hi) {
    u64 r;
    asm("mov.b64 %0, {%1, %2};" : "=l"(r) : "f"(lo), "f"(hi));
    return r;
}

__device__ __forceinline__ float2 unpack2(u64 v) {
    float2 t;
    asm("mov.b64 {%0, %1}, %2;" : "=f"(t.x), "=f"(t.y) : "l"(v));
    return t;
}

__global__ __launch_bounds__(NT, 5)
void ssim_loss_kernel(const float* __restrict__ pred,
                      const float* __restrict__ targ,
                      float* __restrict__ out) {
    __shared__ float2 s_in[INY][43];         // (x, y) interleaved
    __shared__ float4 s_h4[INY][33];         // (hx, hy, hxx, hyy)
    __shared__ float  s_h1[INY][33];         // hxy

    const int tid = threadIdx.x;
    const int tile_x = blockIdx.x * TX;
    const int tile_y = blockIdx.y * TY;
    const int plane = blockIdx.z;

    const float* __restrict__ px = pred + (size_t)plane * IMG_H * IMG_W;
    const float* __restrict__ py = targ + (size_t)plane * IMG_H * IMG_W;
    float* __restrict__ po = out + (size_t)plane * IMG_H * IMG_W;

    // ---- load halo tile, zero-padded ----
    #pragma unroll 1
    for (int idx = tid; idx < INY * INX; idx += NT) {
        int r = idx / INX, cc = idx - r * INX;
        int gr = tile_y + r - PAD;
        int gc = tile_x + cc - PAD;
        float2 v = make_float2(0.f, 0.f);
        if (gr >= 0 && gr < IMG_H && gc >= 0 && gc < IMG_W) {
            size_t off = (size_t)gr * IMG_W + gc;
            v.x = px[off];
            v.y = py[off];
        }
        s_in[r][cc] = v;
    }
    __syncthreads();

    // ---- horizontal blur: 42 rows x 4 chunks of 8 cols = 168 units, one per thread ----
    if (tid < INY * 4) {
        const int r  = tid % INY;
        const int c0 = (tid / INY) * 8;

        u64 a01[8], a23[8];
        float axy[8];
        #pragma unroll
        for (int j = 0; j < 8; j++) { a01[j] = 0ull; a23[j] = 0ull; axy[j] = 0.f; }

        #pragma unroll
        for (int i = 0; i < 18; i++) {
            float2 v = s_in[r][c0 + i];
            u64 vp = pack2(v.x, v.y);
            float xx = v.x * v.x;
            float yy = v.y * v.y;
            float xy = v.x * v.y;
            u64 sq = pack2(xx, yy);
            #pragma unroll
            for (int j = 0; j < 8; j++) {
                const int k = i - j;
                if (k >= 0 && k < WIN) {
                    fma2(a01[j], vp, gwp(k));
                    fma2(a23[j], sq, gwp(k));
                    axy[j] = fmaf(gw(k), xy, axy[j]);
                }
            }
        }
        #pragma unroll
        for (int j = 0; j < 8; j++) {
            float2 p01 = unpack2(a01[j]);
            float2 p23 = unpack2(a23[j]);
            s_h4[r][c0 + j] = make_float4(p01.x, p01.y, p23.x, p23.y);
            s_h1[r][c0 + j] = axy[j];
        }
    }
    __syncthreads();

    // ---- vertical blur: each thread owns 4 output rows of one column ----
    const int c  = tid & (TX - 1);
    const int r0 = (tid >> 5) * 4;     // 0,4,...,28

    u64 a01[4], a23[4];
    float axy[4];
    #pragma unroll
    for (int j = 0; j < 4; j++) { a01[j] = 0ull; a23[j] = 0ull; axy[j] = 0.f; }

    #pragma unroll
    for (int i = 0; i < WIN + 3; i++) {      // rows r0 .. r0+13
        float4 h = s_h4[r0 + i][c];
        float hxy = s_h1[r0 + i][c];
        u64 h01 = pack2(h.x, h.y);
        u64 h23 = pack2(h.z, h.w);
        #pragma unroll
        for (int j = 0; j < 4; j++) {
            const int k = i - j;
            if (k >= 0 && k < WIN) {
                fma2(a01[j], h01, gwp(k));
                fma2(a23[j], h23, gwp(k));
                axy[j] = fmaf(gw(k), hxy, axy[j]);
            }
        }
    }

    // ---- elementwise combine + store ----
    #pragma unroll
    for (int j = 0; j < 4; j++) {
        float2 mu = unpack2(a01[j]);
        float2 e2 = unpack2(a23[j]);
        float mu_x = mu.x, mu_y = mu.y;

        float mxy = mu_x * mu_y;
        float s2x = e2.x - mu_x * mu_x;
        float s2y = e2.y - mu_y * mu_y;
        float sxy = axy[j] - mxy;

        float A1 = 2.f * mxy + C1V;
        float A2 = 2.f * sxy + C2V;
        float B1 = mu_x * mu_x + mu_y * mu_y + C1V;
        float B2 = s2x + s2y + C2V;
        float ssim = __fdividef(A1, B1) * __fdividef(A2, B2);

        float2 v = s_in[r0 + j + PAD][c + PAD];
        float d = v.x - v.y;
        float charb = sqrtf(fmaf(d, d, EPS2));

        float res = A_CHARB * charb + 2.0f * (d * d) + A_SSIM * (1.f - ssim);

        po[(size_t)(tile_y + r0 + j) * IMG_W + (tile_x + c)] = res;
    }
}

extern "C" void kernel_launch(void* const* d_in, const int* in_sizes, int n_in,
                              void* d_out, int out_size) {
    const float* pred = (const float*)d_in[0];
    const float* targ = (const float*)d_in[1];
    float* out = (float*)d_out;

    int planes = in_sizes[0] / (IMG_H * IMG_W);   // 48

    dim3 grid(IMG_W / TX, IMG_H / TY, planes);
    ssim_loss_kernel<<<grid, NT>>>(pred, targ, out);
}